// round 16
// baseline (speedup 1.0000x reference)
#include <cuda_runtime.h>
#include <cstdint>
#include <math.h>

// GRU: B=32, S=2048, E=256, H=256, fp32.
// Kernel 1: gate-input GEMMs xg = x @ {Wz,Wr,Wh} (unchanged).
// Kernel 2: persistent scan, 8 groups x 8-CTA cluster, dual-stream (P,Q).
//   NEW: warp-local reduction. Warp owns 4 columns; lane = (col, k-chunk).
//   Butterfly shfl over 8 k-lanes replaces sP staging + __syncthreads
//   (ZERO CTA barriers in the main loop). Fused R+Z matvec shares h loads.
//   Each lane pushes exactly one b64 message to its fixed peer CTA.

#define SS   2048
#define EE   256
#define HH   256
#define CSZ  8
#define NT   256
#define NGRP 8
#define GRID (NGRP * CSZ)
#define GM   (32 * 2048)

typedef unsigned long long u64;

__device__ float g_gates[(size_t)3 * GM * HH];   // [g][b*S+t][h]

// ---------------- helpers ----------------
__device__ __forceinline__ uint32_t smem_u32(const void* p) {
    uint32_t a;
    asm("{ .reg .u64 t; cvta.to.shared.u64 t, %1; cvt.u32.u64 %0, t; }"
        : "=r"(a) : "l"(p));
    return a;
}
__device__ __forceinline__ void mbar_init(uint32_t a, uint32_t cnt) {
    asm volatile("mbarrier.init.shared.b64 [%0], %1;" :: "r"(a), "r"(cnt) : "memory");
}
__device__ __forceinline__ void mbar_expect(uint32_t a, uint32_t bytes) {
    asm volatile("mbarrier.arrive.expect_tx.shared.b64 _, [%0], %1;"
                 :: "r"(a), "r"(bytes) : "memory");
}
__device__ __forceinline__ void mbar_wait(uint32_t a, uint32_t parity) {
    asm volatile(
        "{\n\t.reg .pred P1;\n\t"
        "WL_%=:\n\t"
        "mbarrier.try_wait.parity.acquire.cta.shared::cta.b64 P1, [%0], %1, 0x989680;\n\t"
        "@P1 bra.uni WD_%=;\n\t"
        "bra.uni WL_%=;\n\t"
        "WD_%=:\n\t}"
        :: "r"(a), "r"(parity) : "memory");
}
__device__ __forceinline__ void cluster_sync_() {
    asm volatile("barrier.cluster.arrive.aligned;" ::: "memory");
    asm volatile("barrier.cluster.wait.aligned;"  ::: "memory");
}
__device__ __forceinline__ u64 pk(float lo, float hi) {
    u64 r; asm("mov.b64 %0, {%1, %2};" : "=l"(r) : "f"(lo), "f"(hi)); return r;
}
__device__ __forceinline__ float hsum(u64 v) {
    float a, b; asm("mov.b64 {%0, %1}, %2;" : "=f"(a), "=f"(b) : "l"(v));
    return a + b;
}
__device__ __forceinline__ void ffma2(u64& d, u64 a, u64 b) {
    asm("fma.rn.f32x2 %0, %1, %2, %0;" : "+l"(d) : "l"(a), "l"(b));
}
__device__ __forceinline__ void st_async_b64(uint32_t addr, u64 v, uint32_t mbar) {
    asm volatile("st.async.shared::cluster.mbarrier::complete_tx::bytes.b64 "
                 "[%0], %1, [%2];"
                 :: "r"(addr), "l"(v), "r"(mbar) : "memory");
}
__device__ __forceinline__ float sigm(float x) {
    return __fdividef(1.f, 1.f + __expf(-x));
}
__device__ __forceinline__ float tanh_(float x) {
    return 1.f - __fdividef(2.f, __expf(2.f * x) + 1.f);
}

// ================= Kernel 1: gate-input GEMMs (unchanged) =================
__global__ void __launch_bounds__(256)
gru_gemm(const float* __restrict__ x, const float* __restrict__ Wz,
         const float* __restrict__ Wr, const float* __restrict__ Wh)
{
    __shared__ float sA[32][128];
    __shared__ float sB[32][64];

    const int mt = blockIdx.x;
    const int gy = blockIdx.y;
    const int g  = gy >> 2, nt = gy & 3;
    const float* W = (g == 0) ? Wz : (g == 1) ? Wr : Wh;
    const int row0 = mt * 128, col0 = nt * 64;

    const int tid = threadIdx.x;
    const int tx = tid & 15;
    const int ty = tid >> 4;

    u64 acc[8][2];
#pragma unroll
    for (int i = 0; i < 8; i++) { acc[i][0] = 0; acc[i][1] = 0; }

    for (int kc = 0; kc < 8; kc++) {
#pragma unroll
        for (int q = 0; q < 4; q++) {
            const int fi = tid + q * 256;
            const int r  = fi >> 3, c = fi & 7;
            const float4 v = *(const float4*)&x[(size_t)(row0 + r) * EE + kc * 32 + c * 4];
            sA[c * 4 + 0][r] = v.x;
            sA[c * 4 + 1][r] = v.y;
            sA[c * 4 + 2][r] = v.z;
            sA[c * 4 + 3][r] = v.w;
        }
#pragma unroll
        for (int q = 0; q < 2; q++) {
            const int fi = tid + q * 256;
            const int r  = fi >> 4, c = fi & 15;
            *(float4*)&sB[r][c * 4] =
                *(const float4*)&W[(size_t)(kc * 32 + r) * HH + col0 + c * 4];
        }
        __syncthreads();
#pragma unroll 8
        for (int k = 0; k < 32; k++) {
            const float4 a0 = *(const float4*)&sA[k][ty * 8];
            const float4 a1 = *(const float4*)&sA[k][ty * 8 + 4];
            const u64 b0 = *(const u64*)&sB[k][tx * 4];
            const u64 b1 = *(const u64*)&sB[k][tx * 4 + 2];
            const float av[8] = {a0.x, a0.y, a0.z, a0.w, a1.x, a1.y, a1.z, a1.w};
#pragma unroll
            for (int i = 0; i < 8; i++) {
                const u64 a2 = pk(av[i], av[i]);
                ffma2(acc[i][0], a2, b0);
                ffma2(acc[i][1], a2, b1);
            }
        }
        __syncthreads();
    }
#pragma unroll
    for (int i = 0; i < 8; i++) {
        const size_t idx = ((size_t)g * GM + row0 + ty * 8 + i) * HH + col0 + tx * 4;
        *(u64*)&g_gates[idx]     = acc[i][0];
        *(u64*)&g_gates[idx + 2] = acc[i][1];
    }
}

// ================= Kernel 2: persistent scan =================
// smem floats:
//  h  [par][s][b][256] = 2048
//  rh [par][s][b][256] = 2048
//  mbars: rh[s*2+par] x4 then h[s*2+par] x4 = 16 floats
#define OFF_H   0
#define OFF_RH  2048
#define OFF_MB  4096
#define MB_RH_B (OFF_MB * 4)
#define MB_H_B  (OFF_MB * 4 + 32)
#define SMEM_FLOATS (OFF_MB + 16)
#define SMEM_BYTES  (SMEM_FLOATS * 4)

extern __shared__ float smem[];

__global__ void __cluster_dims__(CSZ, 1, 1) __launch_bounds__(NT, 1)
gru_scan(const float* __restrict__ h0,
         const float* __restrict__ Uz, const float* __restrict__ Ur,
         const float* __restrict__ Uh, float* __restrict__ out)
{
    const int tid   = threadIdx.x;
    const int rank  = blockIdx.x & (CSZ - 1);
    const int grp   = blockIdx.x >> 3;
    const int b0g   = grp * 4;
    const int jbase = rank * 32;
    const int w     = tid >> 5;
    const int l     = tid & 31;
    const int cl    = w * 4 + (l >> 3);      // local column 0..31
    const int jcol  = jbase + cl;            // global column
    const int kc    = l & 7;                 // k-chunk 0..7 (32 k each)
    const int kp0   = kc * 16;               // u64 k-pair base
    const bool lead = (kc == 0);             // gate-input loader lane

    const uint32_t base_u = smem_u32(smem);

    // U slices: rows k = kc*32 + 2p .. +31, column jcol; k-pairs for FFMA2.
    u64 uz2[16], ur2[16], uh2[16];
#pragma unroll
    for (int p = 0; p < 16; p++) {
        const int k = kc * 32 + 2 * p;
        uz2[p] = pk(Uz[k * HH + jcol], Uz[(k + 1) * HH + jcol]);
        ur2[p] = pk(Ur[k * HH + jcol], Ur[(k + 1) * HH + jcol]);
        uh2[p] = pk(Uh[k * HH + jcol], Uh[(k + 1) * HH + jcol]);
    }
    // h0 (full 256-vector per (s,b)) into parity-0 region
#pragma unroll
    for (int sb = 0; sb < 4; sb++)
        smem[OFF_H + sb * 256 + tid] = h0[(b0g + sb) * HH + tid];
    if (tid == 0) {
#pragma unroll
        for (int i = 0; i < 8; i++)
            mbar_init(base_u + MB_RH_B + i * 8, 1);
    }
    __syncthreads();
    cluster_sync_();

    // fixed destination peer for this lane's messages
    uint32_t peer;
    asm volatile("mapa.shared::cluster.u32 %0, %1, %2;"
                 : "=r"(peer) : "r"(base_u), "r"(kc));
    const int pp = (l >> 4) & 1;             // column-pair within warp
    const int pb = (l >> 3) & 1;             // batch of the message
    // message slot: global column pair (jbase + w*4 + 2pp)
    const uint32_t slot_b = (uint32_t)(((jbase >> 1) + w * 2 + pp) * 8);

    // gate-input prefetch (lead lanes only; 12 values)
    float prer[2][2], prez[2][2], preh[2][2];
#pragma unroll
    for (int s = 0; s < 2; s++)
#pragma unroll
        for (int b = 0; b < 2; b++) {
            const size_t bg = (size_t)(b0g + s * 2 + b) * SS;
            if (lead) {
                prez[s][b] = g_gates[((size_t)0 * GM + bg) * HH + jcol];
                prer[s][b] = g_gates[((size_t)1 * GM + bg) * HH + jcol];
                preh[s][b] = g_gates[((size_t)2 * GM + bg) * HH + jcol];
            } else {
                prez[s][b] = prer[s][b] = preh[s][b] = 0.f;
            }
        }

    float zk[2][2], hld[2][2];

    for (int t = 0; t < SS; t++) {
        const int par = t & 1;
        const int nxt = par ^ 1;
        const uint32_t prh = (uint32_t)((t >> 1) & 1);
        const uint32_t phh = (uint32_t)(((t - 2 + par) >> 1) & 1);

        if (tid == 0) {
#pragma unroll
            for (int s = 0; s < 2; s++) {
                mbar_expect(base_u + MB_RH_B + (s * 2 + par) * 8, 2048);
                if (t + 1 < SS)
                    mbar_expect(base_u + MB_H_B + (s * 2 + nxt) * 8, 2048);
            }
        }

        // ======== Phase A: per stream: wait h, fused R+Z matvec, reduce,
        //          gates, push rh ========
#pragma unroll
        for (int s = 0; s < 2; s++) {
            if (t > 0) mbar_wait(base_u + MB_H_B + (s * 2 + par) * 8, phh);
            const u64* Hb0 = (const u64*)(smem + OFF_H + (par * 2 + s) * 512);
            const u64* Hb1 = Hb0 + 128;
            u64 aR0 = 0, aR1 = 0, aZ0 = 0, aZ1 = 0;
#pragma unroll
            for (int p = 0; p < 16; p++) {
                const u64 h0p = Hb0[kp0 + p], h1p = Hb1[kp0 + p];
                ffma2(aR0, h0p, ur2[p]); ffma2(aR1, h1p, ur2[p]);
                ffma2(aZ0, h0p, uz2[p]); ffma2(aZ1, h1p, uz2[p]);
            }
            float sR0 = hsum(aR0) + prer[s][0];
            float sR1 = hsum(aR1) + prer[s][1];
            float sZ0 = hsum(aZ0) + prez[s][0];
            float sZ1 = hsum(aZ1) + prez[s][1];
#pragma unroll
            for (int d = 1; d <= 4; d <<= 1) {
                sR0 += __shfl_xor_sync(0xffffffffu, sR0, d);
                sR1 += __shfl_xor_sync(0xffffffffu, sR1, d);
                sZ0 += __shfl_xor_sync(0xffffffffu, sZ0, d);
                sZ1 += __shfl_xor_sync(0xffffffffu, sZ1, d);
            }
            const float r0 = sigm(sR0);
            const float r1 = sigm(sR1);
            zk[s][0] = sigm(sZ0);
            zk[s][1] = sigm(sZ1);
            hld[s][0] = smem[OFF_H + (par * 2 + s) * 512 + jcol];
            hld[s][1] = smem[OFF_H + (par * 2 + s) * 512 + 256 + jcol];
            const float rh0 = r0 * hld[s][0];
            const float rh1 = r1 * hld[s][1];
            // push: one message per lane = (pair pp, batch pb) -> rank kc
            const float lo0 = __shfl_sync(0xffffffffu, rh0, pp * 16);
            const float lo1 = __shfl_sync(0xffffffffu, rh1, pp * 16);
            const float hi0 = __shfl_sync(0xffffffffu, rh0, pp * 16 + 8);
            const float hi1 = __shfl_sync(0xffffffffu, rh1, pp * 16 + 8);
            const u64 val = pk(pb ? lo1 : lo0, pb ? hi1 : hi0);
            const uint32_t off =
                (uint32_t)((OFF_RH + ((par * 2 + s) * 2 + pb) * 256) * 4) + slot_b;
            st_async_b64(peer + off, val,
                         peer + (uint32_t)(MB_RH_B + (s * 2 + par) * 8));
        }

        // ======== Phase B: per stream: wait rh, H matvec, reduce, combine,
        //          output, push h(t+1), prefetch gates ========
#pragma unroll
        for (int s = 0; s < 2; s++) {
            mbar_wait(base_u + MB_RH_B + (s * 2 + par) * 8, prh);
            const u64* Rb0 = (const u64*)(smem + OFF_RH + (par * 2 + s) * 512);
            const u64* Rb1 = Rb0 + 128;
            u64 aH0 = 0, aH1 = 0;
#pragma unroll
            for (int p = 0; p < 16; p++) {
                ffma2(aH0, Rb0[kp0 + p], uh2[p]);
                ffma2(aH1, Rb1[kp0 + p], uh2[p]);
            }
            float sH0 = hsum(aH0) + preh[s][0];
            float sH1 = hsum(aH1) + preh[s][1];
#pragma unroll
            for (int d = 1; d <= 4; d <<= 1) {
                sH0 += __shfl_xor_sync(0xffffffffu, sH0, d);
                sH1 += __shfl_xor_sync(0xffffffffu, sH1, d);
            }
            const float hw0 = tanh_(sH0);
            const float hw1 = tanh_(sH1);
            const float hn0 = fmaf(zk[s][0], hw0 - hld[s][0], hld[s][0]);
            const float hn1 = fmaf(zk[s][1], hw1 - hld[s][1], hld[s][1]);
            if ((l & 7) == 0)
                out[((size_t)(b0g + s * 2 + 0) * SS + t) * HH + jcol] = hn0;
            if ((l & 7) == 1)
                out[((size_t)(b0g + s * 2 + 1) * SS + t) * HH + jcol] = hn1;
            if (t + 1 < SS) {
                const float lo0 = __shfl_sync(0xffffffffu, hn0, pp * 16);
                const float lo1 = __shfl_sync(0xffffffffu, hn1, pp * 16);
                const float hi0 = __shfl_sync(0xffffffffu, hn0, pp * 16 + 8);
                const float hi1 = __shfl_sync(0xffffffffu, hn1, pp * 16 + 8);
                const u64 val = pk(pb ? lo1 : lo0, pb ? hi1 : hi0);
                const uint32_t off =
                    (uint32_t)((OFF_H + ((nxt * 2 + s) * 2 + pb) * 256) * 4) + slot_b;
                st_async_b64(peer + off, val,
                             peer + (uint32_t)(MB_H_B + (s * 2 + nxt) * 8));
                if (lead) {
                    const size_t bg0 = (size_t)(b0g + s * 2 + 0) * SS + t + 1;
                    const size_t bg1 = (size_t)(b0g + s * 2 + 1) * SS + t + 1;
                    prez[s][0] = g_gates[((size_t)0 * GM + bg0) * HH + jcol];
                    prez[s][1] = g_gates[((size_t)0 * GM + bg1) * HH + jcol];
                    prer[s][0] = g_gates[((size_t)1 * GM + bg0) * HH + jcol];
                    prer[s][1] = g_gates[((size_t)1 * GM + bg1) * HH + jcol];
                    preh[s][0] = g_gates[((size_t)2 * GM + bg0) * HH + jcol];
                    preh[s][1] = g_gates[((size_t)2 * GM + bg1) * HH + jcol];
                }
            }
        }
    }
    cluster_sync_();   // no CTA exits while inbound traffic could be in flight
}

extern "C" void kernel_launch(void* const* d_in, const int* in_sizes, int n_in,
                              void* d_out, int out_size)
{
    (void)in_sizes; (void)n_in; (void)out_size;
    const float* x  = (const float*)d_in[0];
    const float* h0 = (const float*)d_in[1];
    const float* Wz = (const float*)d_in[2];
    const float* Uz = (const float*)d_in[3];
    const float* Wr = (const float*)d_in[4];
    const float* Ur = (const float*)d_in[5];
    const float* Wh = (const float*)d_in[6];
    const float* Uh = (const float*)d_in[7];
    float* out = (float*)d_out;

    dim3 ggrid(512, 12);
    gru_gemm<<<ggrid, 256>>>(x, Wz, Wr, Wh);

    cudaFuncSetAttribute(gru_scan,
                         cudaFuncAttributeMaxDynamicSharedMemorySize, SMEM_BYTES);
    gru_scan<<<GRID, NT, SMEM_BYTES>>>(h0, Uz, Ur, Uh, out);
}

// round 17
// speedup vs baseline: 5.0037x; 5.0037x over previous
#include <cuda_runtime.h>
#include <cstdint>
#include <math.h>

// GRU: B=32, S=2048, E=256, H=256, fp32.
// Kernel 1: gate-input GEMMs xg = x @ {Wz,Wr,Wh}.
// Kernel 2: persistent scan, 8 groups x 8-CTA cluster, dual-stream (P,Q),
//   U in registers, j-slice ownership, st.async.b64 exchange (r15 structure).
//   R17: batch-packed f32x2 reduction path — producers STS.64 pk(b0,b1),
//   reducers LDS.64 + add.rn.f32x2; r-reduce needs 2 warps (not 4) so
//   warps 2-3 start phase Z (the rh-flight hider) immediately.

#define SS   2048
#define EE   256
#define HH   256
#define CSZ  8
#define NT   256
#define NGRP 8
#define GRID (NGRP * CSZ)
#define GM   (32 * 2048)

typedef unsigned long long u64;

__device__ float g_gates[(size_t)3 * GM * HH];   // [g][b*S+t][h]

// ---------------- helpers ----------------
__device__ __forceinline__ uint32_t smem_u32(const void* p) {
    uint32_t a;
    asm("{ .reg .u64 t; cvta.to.shared.u64 t, %1; cvt.u32.u64 %0, t; }"
        : "=r"(a) : "l"(p));
    return a;
}
__device__ __forceinline__ void mbar_init(uint32_t a, uint32_t cnt) {
    asm volatile("mbarrier.init.shared.b64 [%0], %1;" :: "r"(a), "r"(cnt) : "memory");
}
__device__ __forceinline__ void mbar_expect(uint32_t a, uint32_t bytes) {
    asm volatile("mbarrier.arrive.expect_tx.shared.b64 _, [%0], %1;"
                 :: "r"(a), "r"(bytes) : "memory");
}
__device__ __forceinline__ void mbar_wait(uint32_t a, uint32_t parity) {
    asm volatile(
        "{\n\t.reg .pred P1;\n\t"
        "WL_%=:\n\t"
        "mbarrier.try_wait.parity.acquire.cta.shared::cta.b64 P1, [%0], %1, 0x989680;\n\t"
        "@P1 bra.uni WD_%=;\n\t"
        "bra.uni WL_%=;\n\t"
        "WD_%=:\n\t}"
        :: "r"(a), "r"(parity) : "memory");
}
__device__ __forceinline__ void cluster_sync_() {
    asm volatile("barrier.cluster.arrive.aligned;" ::: "memory");
    asm volatile("barrier.cluster.wait.aligned;"  ::: "memory");
}
__device__ __forceinline__ u64 pk(float lo, float hi) {
    u64 r; asm("mov.b64 %0, {%1, %2};" : "=l"(r) : "f"(lo), "f"(hi)); return r;
}
__device__ __forceinline__ float hsum(u64 v) {
    float a, b; asm("mov.b64 {%0, %1}, %2;" : "=f"(a), "=f"(b) : "l"(v));
    return a + b;
}
__device__ __forceinline__ void unpk(u64 v, float& a, float& b) {
    asm("mov.b64 {%0, %1}, %2;" : "=f"(a), "=f"(b) : "l"(v));
}
__device__ __forceinline__ void ffma2(u64& d, u64 a, u64 b) {
    asm("fma.rn.f32x2 %0, %1, %2, %0;" : "+l"(d) : "l"(a), "l"(b));
}
__device__ __forceinline__ u64 addx2(u64 a, u64 b) {
    u64 r; asm("add.rn.f32x2 %0, %1, %2;" : "=l"(r) : "l"(a), "l"(b)); return r;
}
// send packed 8B to same smem offset in all cluster CTAs; moff_b = byte offset
// of the tx-accounting mbarrier from each CTA's smem base.
__device__ __forceinline__ void push8_b64(uint32_t base_u, uint32_t off_b,
                                          u64 v, uint32_t moff_b) {
#pragma unroll
    for (int r = 0; r < CSZ; r++) {
        uint32_t ra;
        asm volatile("mapa.shared::cluster.u32 %0, %1, %2;"
                     : "=r"(ra) : "r"(base_u), "r"(r));
        asm volatile("st.async.shared::cluster.mbarrier::complete_tx::bytes.b64 "
                     "[%0], %1, [%2];"
                     :: "r"(ra + off_b), "l"(v), "r"(ra + moff_b) : "memory");
    }
}

// ================= Kernel 1: gate-input GEMMs (unchanged) =================
__global__ void __launch_bounds__(256)
gru_gemm(const float* __restrict__ x, const float* __restrict__ Wz,
         const float* __restrict__ Wr, const float* __restrict__ Wh)
{
    __shared__ float sA[32][128];
    __shared__ float sB[32][64];

    const int mt = blockIdx.x;
    const int gy = blockIdx.y;
    const int g  = gy >> 2, nt = gy & 3;
    const float* W = (g == 0) ? Wz : (g == 1) ? Wr : Wh;
    const int row0 = mt * 128, col0 = nt * 64;

    const int tid = threadIdx.x;
    const int tx = tid & 15;
    const int ty = tid >> 4;

    u64 acc[8][2];
#pragma unroll
    for (int i = 0; i < 8; i++) { acc[i][0] = 0; acc[i][1] = 0; }

    for (int kc = 0; kc < 8; kc++) {
#pragma unroll
        for (int q = 0; q < 4; q++) {
            const int fi = tid + q * 256;
            const int r  = fi >> 3, c = fi & 7;
            const float4 v = *(const float4*)&x[(size_t)(row0 + r) * EE + kc * 32 + c * 4];
            sA[c * 4 + 0][r] = v.x;
            sA[c * 4 + 1][r] = v.y;
            sA[c * 4 + 2][r] = v.z;
            sA[c * 4 + 3][r] = v.w;
        }
#pragma unroll
        for (int q = 0; q < 2; q++) {
            const int fi = tid + q * 256;
            const int r  = fi >> 4, c = fi & 15;
            *(float4*)&sB[r][c * 4] =
                *(const float4*)&W[(size_t)(kc * 32 + r) * HH + col0 + c * 4];
        }
        __syncthreads();
#pragma unroll 8
        for (int k = 0; k < 32; k++) {
            const float4 a0 = *(const float4*)&sA[k][ty * 8];
            const float4 a1 = *(const float4*)&sA[k][ty * 8 + 4];
            const u64 b0 = *(const u64*)&sB[k][tx * 4];
            const u64 b1 = *(const u64*)&sB[k][tx * 4 + 2];
            const float av[8] = {a0.x, a0.y, a0.z, a0.w, a1.x, a1.y, a1.z, a1.w};
#pragma unroll
            for (int i = 0; i < 8; i++) {
                const u64 a2 = pk(av[i], av[i]);
                ffma2(acc[i][0], a2, b0);
                ffma2(acc[i][1], a2, b1);
            }
        }
        __syncthreads();
    }
#pragma unroll
    for (int i = 0; i < 8; i++) {
        const size_t idx = ((size_t)g * GM + row0 + ty * 8 + i) * HH + col0 + tx * 4;
        *(u64*)&g_gates[idx]     = acc[i][0];
        *(u64*)&g_gates[idx + 2] = acc[i][1];
    }
}

// ================= Kernel 2: persistent scan, dual-stream =================
// smem floats:
//  h  [par][s][b][256] = 2048
//  rh [par][s][b][256] = 2048
//  sPu (u64): R [s][8q][32j] = 512 u64; Z at +512; H at +1024 -> 1536 u64
//  mbars: rh[s*2+par] x4 then h[s*2+par] x4
#define OFF_H   0
#define OFF_RH  2048
#define OFF_P   4096                  // float offset; 1536 u64 = 3072 floats
#define OFF_MB  7168
#define MB_RH_B (OFF_MB * 4)
#define MB_H_B  (OFF_MB * 4 + 32)
#define SMEM_FLOATS (OFF_MB + 16)
#define SMEM_BYTES  (SMEM_FLOATS * 4)

extern __shared__ float smem[];

__global__ void __cluster_dims__(CSZ, 1, 1) __launch_bounds__(NT, 1)
gru_scan(const float* __restrict__ h0,
         const float* __restrict__ Uz, const float* __restrict__ Ur,
         const float* __restrict__ Uh, float* __restrict__ out)
{
    const int tid   = threadIdx.x;
    const int rank  = blockIdx.x & (CSZ - 1);
    const int grp   = blockIdx.x >> 3;
    const int b0g   = grp * 4;                 // 4 batches per group
    const int jbase = rank * 32;
    const int j     = tid & 31;
    const int ks    = tid >> 5;
    const int k0    = ks * 32;
    const int ks16  = ks * 16;
    const int jcol  = jbase + j;

    u64* sPu = (u64*)(smem + OFF_P);

    const uint32_t base_u = smem_u32(smem);

    // U slices (rows k0..k0+31, column jcol), k-pairs packed for FFMA2.
    u64 uz2[16], ur2[16], uh2[16];
#pragma unroll
    for (int p = 0; p < 16; p++) {
        const int k = k0 + 2 * p;
        uz2[p] = pk(Uz[k * HH + jcol], Uz[(k + 1) * HH + jcol]);
        ur2[p] = pk(Ur[k * HH + jcol], Ur[(k + 1) * HH + jcol]);
        uh2[p] = pk(Uh[k * HH + jcol], Uh[(k + 1) * HH + jcol]);
    }
    // h0 into parity-0 buffers; layout [par][s][b][256]
#pragma unroll
    for (int sb = 0; sb < 4; sb++)
        smem[OFF_H + sb * 256 + tid] = h0[(b0g + sb) * HH + tid];
    if (tid == 0) {
#pragma unroll
        for (int i = 0; i < 8; i++)
            mbar_init(base_u + MB_RH_B + i * 8, 1);
    }
    __syncthreads();
    cluster_sync_();

    // gate-input prefetch (role-partitioned, both batches per lane):
    //  reduce warps 0-1 (tid<64): s=tid>>5 -> pre_r[b]
    //  combine warps 4-5 (128<=tid<192): s=(tid-128)>>5 -> pre_z[b], pre_h[b]
    float pre_r[2] = {0.f, 0.f}, pre_z[2] = {0.f, 0.f}, pre_h[2] = {0.f, 0.f};
    if (tid < 64) {
        const int s = tid >> 5, jj = tid & 31;
#pragma unroll
        for (int b = 0; b < 2; b++)
            pre_r[b] = g_gates[((size_t)1 * GM + (size_t)(b0g + s * 2 + b) * SS) * HH
                               + jbase + jj];
    } else if (tid >= 128 && tid < 192) {
        const int s = (tid - 128) >> 5, jj = tid & 31;
#pragma unroll
        for (int b = 0; b < 2; b++) {
            pre_z[b] = g_gates[((size_t)0 * GM + (size_t)(b0g + s * 2 + b) * SS) * HH
                               + jbase + jj];
            pre_h[b] = g_gates[((size_t)2 * GM + (size_t)(b0g + s * 2 + b) * SS) * HH
                               + jbase + jj];
        }
    }

    for (int t = 0; t < SS; t++) {
        const int par = t & 1;
        const int nxt = par ^ 1;
        const uint32_t prh = (uint32_t)((t >> 1) & 1);
        const uint32_t ph  = (uint32_t)(((t - 2 + par) >> 1) & 1);

        if (tid == 0) {
#pragma unroll
            for (int s = 0; s < 2; s++) {
                mbar_expect(base_u + MB_RH_B + (s * 2 + par) * 8, 2048);
                if (t + 1 < SS)
                    mbar_expect(base_u + MB_H_B + (s * 2 + nxt) * 8, 2048);
            }
        }

        // ---- phase R for both streams (wait h, matvec, batch-packed STS.64) --
#pragma unroll
        for (int s = 0; s < 2; s++) {
            if (t > 0) mbar_wait(base_u + MB_H_B + (s * 2 + par) * 8, ph);
            const u64* Hb0 = (const u64*)(smem + OFF_H + (par * 2 + s) * 512);
            const u64* Hb1 = Hb0 + 128;
            u64 a0 = 0, a1 = 0;
#pragma unroll
            for (int p = 0; p < 16; p++) {
                ffma2(a0, Hb0[ks16 + p], ur2[p]);
                ffma2(a1, Hb1[ks16 + p], ur2[p]);
            }
            sPu[s * 256 + tid] = pk(hsum(a0), hsum(a1));
        }
        __syncthreads();

        // ---- r reduce (warps 0-1; lane = (stream, column), both batches) ----
        if (tid < 64) {
            const int s = tid >> 5, jj = tid & 31;
            const u64* P = sPu + s * 256 + jj;
            u64 acc = addx2(addx2(P[0], P[32]), addx2(P[64], P[96]));
            acc = addx2(acc, addx2(addx2(P[128], P[160]), addx2(P[192], P[224])));
            float s0, s1; unpk(acc, s0, s1);
            const float r0 = __fdividef(1.f, 1.f + __expf(-(s0 + pre_r[0])));
            const float r1 = __fdividef(1.f, 1.f + __expf(-(s1 + pre_r[1])));
            const float h0v = smem[OFF_H + ((par * 2 + s) * 2 + 0) * 256 + jbase + jj];
            const float h1v = smem[OFF_H + ((par * 2 + s) * 2 + 1) * 256 + jbase + jj];
            const float rh0 = r0 * h0v;
            const float rh1 = r1 * h1v;
            const float rh0n = __shfl_down_sync(0xffffffffu, rh0, 1);
            const float rh1n = __shfl_down_sync(0xffffffffu, rh1, 1);
            if ((jj & 1) == 0) {
                const uint32_t off0 =
                    (uint32_t)(OFF_RH + ((par * 2 + s) * 2 + 0) * 256 + jbase + jj) * 4;
                const uint32_t off1 =
                    (uint32_t)(OFF_RH + ((par * 2 + s) * 2 + 1) * 256 + jbase + jj) * 4;
                const uint32_t mo = (uint32_t)(MB_RH_B + (s * 2 + par) * 8);
                push8_b64(base_u, off0, pk(rh0, rh0n), mo);
                push8_b64(base_u, off1, pk(rh1, rh1n), mo);
            }
            if (t + 1 < SS) {
#pragma unroll
                for (int b = 0; b < 2; b++)
                    pre_r[b] = g_gates[((size_t)1 * GM
                               + (size_t)(b0g + s * 2 + b) * SS + t + 1) * HH
                               + jbase + jj];
            }
        }

        // ---- phase Z for both streams (hides rh flights) ----
#pragma unroll
        for (int s = 0; s < 2; s++) {
            const u64* Hb0 = (const u64*)(smem + OFF_H + (par * 2 + s) * 512);
            const u64* Hb1 = Hb0 + 128;
            u64 a0 = 0, a1 = 0;
#pragma unroll
            for (int p = 0; p < 16; p++) {
                ffma2(a0, Hb0[ks16 + p], uz2[p]);
                ffma2(a1, Hb1[ks16 + p], uz2[p]);
            }
            sPu[512 + s * 256 + tid] = pk(hsum(a0), hsum(a1));
        }

        // ---- phase H for both streams (wait rh, matvec) ----
#pragma unroll
        for (int s = 0; s < 2; s++) {
            mbar_wait(base_u + MB_RH_B + (s * 2 + par) * 8, prh);
            const u64* Rb0 = (const u64*)(smem + OFF_RH + (par * 2 + s) * 512);
            const u64* Rb1 = Rb0 + 128;
            u64 a0 = 0, a1 = 0;
#pragma unroll
            for (int p = 0; p < 16; p++) {
                ffma2(a0, Rb0[ks16 + p], uh2[p]);
                ffma2(a1, Rb1[ks16 + p], uh2[p]);
            }
            sPu[1024 + s * 256 + tid] = pk(hsum(a0), hsum(a1));
        }
        __syncthreads();

        // ---- combine (warps 4-5; lane = (stream, column), both batches) ----
        if (tid >= 128 && tid < 192) {
            const int s = (tid - 128) >> 5, jj = tid & 31;
            const u64* PZ = sPu + 512 + s * 256 + jj;
            const u64* PHh = sPu + 1024 + s * 256 + jj;
            u64 az = addx2(addx2(PZ[0], PZ[32]), addx2(PZ[64], PZ[96]));
            az = addx2(az, addx2(addx2(PZ[128], PZ[160]), addx2(PZ[192], PZ[224])));
            u64 ah = addx2(addx2(PHh[0], PHh[32]), addx2(PHh[64], PHh[96]));
            ah = addx2(ah, addx2(addx2(PHh[128], PHh[160]), addx2(PHh[192], PHh[224])));
            float z0, z1, hh0, hh1;
            unpk(az, z0, z1); unpk(ah, hh0, hh1);
            const float zg0 = __fdividef(1.f, 1.f + __expf(-(z0 + pre_z[0])));
            const float zg1 = __fdividef(1.f, 1.f + __expf(-(z1 + pre_z[1])));
            const float hw0 = 1.f - __fdividef(2.f, __expf(2.f * (hh0 + pre_h[0])) + 1.f);
            const float hw1 = 1.f - __fdividef(2.f, __expf(2.f * (hh1 + pre_h[1])) + 1.f);
            const float ho0 = smem[OFF_H + ((par * 2 + s) * 2 + 0) * 256 + jbase + jj];
            const float ho1 = smem[OFF_H + ((par * 2 + s) * 2 + 1) * 256 + jbase + jj];
            const float hn0 = fmaf(zg0, hw0 - ho0, ho0);
            const float hn1 = fmaf(zg1, hw1 - ho1, ho1);
            out[((size_t)(b0g + s * 2 + 0) * SS + t) * HH + jbase + jj] = hn0;
            out[((size_t)(b0g + s * 2 + 1) * SS + t) * HH + jbase + jj] = hn1;
            if (t + 1 < SS) {
                const float hn0n = __shfl_down_sync(0xffffffffu, hn0, 1);
                const float hn1n = __shfl_down_sync(0xffffffffu, hn1, 1);
                if ((jj & 1) == 0) {
                    const uint32_t off0 =
                        (uint32_t)(OFF_H + ((nxt * 2 + s) * 2 + 0) * 256 + jbase + jj) * 4;
                    const uint32_t off1 =
                        (uint32_t)(OFF_H + ((nxt * 2 + s) * 2 + 1) * 256 + jbase + jj) * 4;
                    const uint32_t mo = (uint32_t)(MB_H_B + (s * 2 + nxt) * 8);
                    push8_b64(base_u, off0, pk(hn0, hn0n), mo);
                    push8_b64(base_u, off1, pk(hn1, hn1n), mo);
                }
#pragma unroll
                for (int b = 0; b < 2; b++) {
                    pre_z[b] = g_gates[((size_t)0 * GM
                               + (size_t)(b0g + s * 2 + b) * SS + t + 1) * HH
                               + jbase + jj];
                    pre_h[b] = g_gates[((size_t)2 * GM
                               + (size_t)(b0g + s * 2 + b) * SS + t + 1) * HH
                               + jbase + jj];
                }
            }
        }
    }
    cluster_sync_();   // no CTA exits while inbound traffic could be in flight
}

extern "C" void kernel_launch(void* const* d_in, const int* in_sizes, int n_in,
                              void* d_out, int out_size)
{
    (void)in_sizes; (void)n_in; (void)out_size;
    const float* x  = (const float*)d_in[0];
    const float* h0 = (const float*)d_in[1];
    const float* Wz = (const float*)d_in[2];
    const float* Uz = (const float*)d_in[3];
    const float* Wr = (const float*)d_in[4];
    const float* Ur = (const float*)d_in[5];
    const float* Wh = (const float*)d_in[6];
    const float* Uh = (const float*)d_in[7];
    float* out = (float*)d_out;

    dim3 ggrid(512, 12);
    gru_gemm<<<ggrid, 256>>>(x, Wz, Wr, Wh);

    cudaFuncSetAttribute(gru_scan,
                         cudaFuncAttributeMaxDynamicSharedMemorySize, SMEM_BYTES);
    gru_scan<<<GRID, NT, SMEM_BYTES>>>(h0, Uz, Ur, Uh, out);
}